// round 4
// baseline (speedup 1.0000x reference)
#include <cuda_runtime.h>
#include <cstdint>

#define BB 256
#define TT 199
#define QQ 1000
#define NROW (BB * TT)                // 50,944
#define NEL  ((size_t)NROW * QQ)      // 50,944,000

// Scratch (__device__ globals; zero-initialized at load; the last block of
// each launch resets them, so every graph replay starts from zero).
__device__ double       g_bsum[BB];
__device__ int          g_bcnt[BB];
__device__ unsigned int g_ticket;

// One block (256 threads) per (b, t) row of 1000 floats = 250 float4.
__global__ __launch_bounds__(256) void row_kernel(
    const float* __restrict__ pred,    // (B, T, Q)
    const float* __restrict__ batch,   // (B, T+1, Q)
    float* __restrict__ out)
{
    const int t    = blockIdx.x;
    const int b    = blockIdx.y;
    const int tid  = threadIdx.x;
    const int lane = tid & 31;
    const int wid  = tid >> 5;
    const bool act = tid < 250;

    const size_t row = (size_t)b * TT + t;
    const float4* __restrict__ gt4 =
        (const float4*)(batch + ((size_t)b * (TT + 1) + (t + 1)) * QQ);
    const float4* __restrict__ pr4 =
        (const float4*)(pred + row * QQ);

    __shared__ float  s_p[QQ];
    __shared__ float  s_g[QQ];
    __shared__ int    s_w[8];
    __shared__ float  s_red[8];
    __shared__ int    s_last;
    __shared__ double s_d[BB];

    // ---- unconditional up-front vector loads (max MLP, no serialization) ----
    float4 g = make_float4(0.f, 0.f, 0.f, 0.f);
    float4 p = make_float4(0.f, 0.f, 0.f, 0.f);
    if (act) { g = gt4[tid]; p = pr4[tid]; }

    // stage raw values to smem (mask applied at store time)
    if (act) {
        int q = tid * 4;
        s_p[q+0] = p.x; s_p[q+1] = p.y; s_p[q+2] = p.z; s_p[q+3] = p.w;
        s_g[q+0] = g.x; s_g[q+1] = g.y; s_g[q+2] = g.z; s_g[q+3] = g.w;
    }

    // block-wide any(g == 1)
    int anyv = (g.x == 1.0f) | (g.y == 1.0f) | (g.z == 1.0f) | (g.w == 1.0f);
    unsigned wany = __ballot_sync(0xFFFFFFFFu, anyv);
    if (lane == 0) s_w[wid] = (wany != 0);

    // bce from registers (dummy lanes contribute exactly 0: g=0,p=0 ->
    // 0*max(log 0,-100) + 1*log(1-0) = 0). p in (0.01,0.99) so no NaN.
    float lsum;
    {
        float lp, l1, s = 0.0f;
        lp = fmaxf(__logf(p.x), -100.0f); l1 = fmaxf(__logf(1.0f - p.x), -100.0f);
        s += g.x * lp + (1.0f - g.x) * l1;
        lp = fmaxf(__logf(p.y), -100.0f); l1 = fmaxf(__logf(1.0f - p.y), -100.0f);
        s += g.y * lp + (1.0f - g.y) * l1;
        lp = fmaxf(__logf(p.z), -100.0f); l1 = fmaxf(__logf(1.0f - p.z), -100.0f);
        s += g.z * lp + (1.0f - g.z) * l1;
        lp = fmaxf(__logf(p.w), -100.0f); l1 = fmaxf(__logf(1.0f - p.w), -100.0f);
        s += g.w * lp + (1.0f - g.w) * l1;
        lsum = s;
    }
    #pragma unroll
    for (int off = 16; off > 0; off >>= 1)
        lsum += __shfl_down_sync(0xFFFFFFFFu, lsum, off);
    if (lane == 0) s_red[wid] = lsum;

    __syncthreads();   // the ONLY block sync in the hot path

    const int masked = s_w[0] | s_w[1] | s_w[2] | s_w[3] |
                       s_w[4] | s_w[5] | s_w[6] | s_w[7];
    const float fm = masked ? 1.0f : 0.0f;

    // ---- shifted aligned vector stores (output region starts at +1 elem) ----
    float* __restrict__ outp = out + 1 + row * QQ;   // elem offset == 1 (mod 4)
    float* __restrict__ outg = outp + NEL;
    if (tid < 249) {
        int q = 3 + tid * 4;                          // 16B-aligned at outp+q
        float4 vp = make_float4(s_p[q]*fm, s_p[q+1]*fm, s_p[q+2]*fm, s_p[q+3]*fm);
        float4 vg = make_float4(s_g[q]*fm, s_g[q+1]*fm, s_g[q+2]*fm, s_g[q+3]*fm);
        *(float4*)(outp + q) = vp;
        *(float4*)(outg + q) = vg;
    } else if (tid == 249) {
        outp[0] = s_p[0]*fm; outp[1] = s_p[1]*fm; outp[2] = s_p[2]*fm;
        outp[999] = s_p[999]*fm;
    } else if (tid == 250) {
        outg[0] = s_g[0]*fm; outg[1] = s_g[1]*fm; outg[2] = s_g[2]*fm;
        outg[999] = s_g[999]*fm;
    } else if (tid == 251) {
        out[1 + 2 * NEL + row] = fm;                  // row_mask
    }

    // ---- per-batch accumulation + ticket ----
    if (tid < 32) {
        float v = (tid < 8) ? s_red[tid] : 0.0f;
        #pragma unroll
        for (int off = 4; off > 0; off >>= 1)
            v += __shfl_down_sync(0xFFFFFFFFu, v, off);
        if (tid == 0) {
            if (masked) {
                atomicAdd(&g_bsum[b], (double)(-v));
                atomicAdd(&g_bcnt[b], 1);
            }
            __threadfence();
            unsigned done = atomicAdd(&g_ticket, 1u);
            s_last = (done == (unsigned)(NROW - 1));
        }
    }
    __syncthreads();

    // ---- last block: finalize loss, reset scratch ----
    if (s_last) {
        __threadfence();   // acquire: see all other blocks' atomics
        const int c = g_bcnt[tid];
        s_d[tid] = (c > 0) ? (g_bsum[tid] / ((double)c * (double)QQ)) : 0.0;
        __syncthreads();
        #pragma unroll
        for (int off = BB / 2; off > 0; off >>= 1) {
            if (tid < off) s_d[tid] += s_d[tid + off];
            __syncthreads();
        }
        if (tid == 0) {
            out[0] = (float)s_d[0];
            g_ticket = 0u;
        }
        g_bsum[tid] = 0.0;   // reset for next graph replay
        g_bcnt[tid] = 0;
    }
}

extern "C" void kernel_launch(void* const* d_in, const int* in_sizes, int n_in,
                              void* d_out, int out_size) {
    const float* pred  = (const float*)d_in[0];
    const float* batch = (const float*)d_in[1];
    float* out = (float*)d_out;

    dim3 grid(TT, BB);
    row_kernel<<<grid, 256>>>(pred, batch, out);
}